// round 2
// baseline (speedup 1.0000x reference)
#include <cuda_runtime.h>
#include <math.h>

#define D   64
#define C3  192
#define CC  384
#define MAXN 100352
#define MAXE 1600064

// ---------------- device scratch (static, no allocation) ----------------
__device__ float d_xA[MAXN * D];
__device__ float d_xB[MAXN * D];
__device__ float d_S [MAXN * D];
__device__ float d_C [MAXN * CC];          // gi|gh scratch  (~154MB)
__device__ int   d_indeg[MAXN];
__device__ int   d_off  [MAXN];
__device__ int   d_cur  [MAXN];
__device__ int   d_csrc [MAXE];
__device__ float d_Bcat[3][D * CC];        // per layer l=2..4: [k][0:192]=A=W@Wih^T, [k][192+t]=Whh[t][k]
__device__ float d_q[C3], d_p2[C3], d_x1row[D];
__device__ float d_pool[64 * D];

__device__ __forceinline__ float sigf(float x) { return 1.0f / (1.0f + expf(-x)); }

// ---------------- CSR build ----------------
__global__ void k_init(int N) {
    int i = blockIdx.x * blockDim.x + threadIdx.x;
    if (i < N) d_indeg[i] = 0;
    if (i < 64 * D) d_pool[i] = 0.0f;
}

__global__ void k_count(const int* __restrict__ ei, int E) {
    int i = blockIdx.x * blockDim.x + threadIdx.x;
    if (i < E) atomicAdd(&d_indeg[ei[E + i]], 1);
}

// single-block exclusive scan over indegree -> d_off, d_cur
__global__ void k_scan(int N) {
    __shared__ int sm[1024];
    int t = threadIdx.x;
    int chunk = (N + 1023) >> 10;
    int b = t * chunk, e = min(N, b + chunk);
    int s = 0;
    for (int i = b; i < e; i++) s += d_indeg[i];
    sm[t] = s;
    __syncthreads();
    for (int off = 1; off < 1024; off <<= 1) {
        int v = (t >= off) ? sm[t - off] : 0;
        __syncthreads();
        sm[t] += v;
        __syncthreads();
    }
    int run = sm[t] - s;   // exclusive prefix
    for (int i = b; i < e; i++) {
        d_off[i] = run;
        d_cur[i] = run;
        run += d_indeg[i];
    }
}

__global__ void k_fill(const int* __restrict__ ei, int E) {
    int i = blockIdx.x * blockDim.x + threadIdx.x;
    if (i < E) {
        int s = ei[i];
        int d = ei[E + i];
        int p = atomicAdd(&d_cur[d], 1);
        d_csrc[p] = s;
    }
}

// ---------------- layers 1+2 analytic shortcuts ----------------
// Layer1: x0=0 -> x1 is one constant row. Also precompute layer2 constants:
//   m2 = x1 @ W1; q = m2 @ Wih1^T; p2 = x1 @ Whh1^T + bhh1
__global__ void k_const(const float* __restrict__ convw,
                        const float* __restrict__ wih,
                        const float* __restrict__ whh,
                        const float* __restrict__ bih,
                        const float* __restrict__ bhh) {
    __shared__ float x1[D], m2[D];
    int t = threadIdx.x;
    if (t < D) {
        float r = sigf(bih[t] + bhh[t]);
        float z = sigf(bih[64 + t] + bhh[64 + t]);
        float n = tanhf(bih[128 + t] + r * bhh[128 + t]);
        x1[t] = (1.0f - z) * n;
    }
    __syncthreads();
    if (t < D) {
        const float* w1 = convw + 1 * D * D;   // layer index 1
        float s = 0.0f;
        for (int k = 0; k < D; k++) s += x1[k] * w1[k * D + t];
        m2[t] = s;
        d_x1row[t] = x1[t];
    }
    __syncthreads();
    if (t < C3) {
        const float* wih1 = wih + 1 * C3 * D;
        const float* whh1 = whh + 1 * C3 * D;
        const float* bhh1 = bhh + 1 * C3;
        float sq = 0.0f, sp = 0.0f;
        for (int j = 0; j < D; j++) {
            sq += m2[j] * wih1[t * D + j];
            sp += x1[j] * whh1[t * D + j];
        }
        d_q[t]  = sq;
        d_p2[t] = sp + bhh1[t];
    }
}

// Layer2: x2[v] is a function of indegree only. Writes into d_xA.
__global__ void k_layer2(const float* __restrict__ bih1, int N) {
    int idx = blockIdx.x * blockDim.x + threadIdx.x;
    if (idx >= N * D) return;
    int v = idx >> 6, d = idx & 63;
    float deg = (float)d_indeg[v];
    float r = sigf(deg * d_q[d]       + bih1[d]       + d_p2[d]);
    float z = sigf(deg * d_q[64 + d]  + bih1[64 + d]  + d_p2[64 + d]);
    float n = tanhf(deg * d_q[128 + d] + bih1[128 + d] + r * d_p2[128 + d]);
    d_xA[idx] = (1.0f - z) * n + z * d_x1row[d];
}

// ---------------- precompute Bcat for layers 2..4 (0-indexed) ----------------
__global__ void k_bcat(const float* __restrict__ convw,
                       const float* __restrict__ wih,
                       const float* __restrict__ whh) {
    int idx = blockIdx.x * blockDim.x + threadIdx.x;
    if (idx >= 3 * D * CC) return;
    int l0 = idx / (D * CC);
    int rem = idx - l0 * (D * CC);
    int k = rem / CC;
    int c = rem - k * CC;
    int lg = l0 + 2;
    float val;
    if (c < C3) {
        const float* w  = convw + lg * D * D;
        const float* wi = wih   + lg * C3 * D;
        float s = 0.0f;
        for (int j = 0; j < D; j++) s += w[k * D + j] * wi[c * D + j];
        val = s;
    } else {
        val = whh[lg * C3 * D + (c - C3) * D + k];
    }
    d_Bcat[l0][k * CC + c] = val;
}

// ---------------- gather: S[v] = sum_{u in in(v)} x[u] ----------------
__global__ void k_gather(int cur, int N) {
    int w = (blockIdx.x * blockDim.x + threadIdx.x) >> 5;
    int lane = threadIdx.x & 31;
    if (w >= N) return;
    const float* x = cur ? d_xB : d_xA;
    int o = d_off[w], dg = d_indeg[w];
    float2 acc = make_float2(0.0f, 0.0f);
    for (int e = 0; e < dg; e++) {
        int u = d_csrc[o + e];
        float2 v = ((const float2*)(x + u * D))[lane];
        acc.x += v.x;
        acc.y += v.y;
    }
    ((float2*)(d_S + w * D))[lane] = acc;
}

// ---------------- fused GEMM: C[n][0:192]=S@A, C[n][192:384]=x@Whh^T ----------------
// block: 256 threads = 8 node-groups x 32 col-groups; thread tile = 8 nodes x 12 cols
__global__ void __launch_bounds__(256) k_gemm(int cur, int l, int N) {
    __shared__ float sA[64 * 128];   // 32KB: [n][0:64]=S row, [n][64:128]=x row
    const float* X = cur ? d_xB : d_xA;
    const float* __restrict__ B = d_Bcat[l];
    int ntiles = (N + 63) >> 6;
    int ty = threadIdx.x >> 5;        // 0..7  -> nodes ty*8..ty*8+7
    int cx = threadIdx.x & 31;        // cols cx + 32*j, j=0..11
    for (int tile = blockIdx.x; tile < ntiles; tile += gridDim.x) {
        int n0 = tile << 6;
        __syncthreads();
        for (int i = threadIdx.x; i < 2048; i += 256) {
            int n = i >> 5, q = i & 31;
            float4 v = make_float4(0.f, 0.f, 0.f, 0.f);
            int gn = n0 + n;
            if (gn < N) {
                if (q < 16) v = ((const float4*)d_S)[gn * 16 + q];
                else        v = ((const float4*)X)[gn * 16 + (q - 16)];
            }
            ((float4*)sA)[n * 32 + q] = v;
        }
        __syncthreads();

        float acc[8][12];
        #pragma unroll
        for (int i = 0; i < 8; i++)
            #pragma unroll
            for (int j = 0; j < 12; j++) acc[i][j] = 0.0f;

        int nb = ty * 8;
        #pragma unroll 8
        for (int k = 0; k < 64; k++) {
            float aS[8], aX[8], b[12];
            #pragma unroll
            for (int i = 0; i < 8; i++) {
                aS[i] = sA[(nb + i) * 128 + k];
                aX[i] = sA[(nb + i) * 128 + 64 + k];
            }
            #pragma unroll
            for (int j = 0; j < 12; j++) b[j] = __ldg(&B[k * CC + cx + 32 * j]);
            #pragma unroll
            for (int i = 0; i < 8; i++) {
                #pragma unroll
                for (int j = 0; j < 6; j++)  acc[i][j] += aS[i] * b[j];
                #pragma unroll
                for (int j = 6; j < 12; j++) acc[i][j] += aX[i] * b[j];
            }
        }
        for (int i = 0; i < 8; i++) {
            int n = n0 + nb + i;
            if (n < N) {
                #pragma unroll
                for (int j = 0; j < 12; j++) d_C[n * CC + cx + 32 * j] = acc[i][j];
            }
        }
    }
}

// ---------------- GRU elementwise ----------------
__global__ void k_gru(int cur, const float* __restrict__ bih,
                      const float* __restrict__ bhh, int N) {
    int idx = blockIdx.x * blockDim.x + threadIdx.x;
    if (idx >= N * D) return;
    int v = idx >> 6, d = idx & 63;
    const float* xin = cur ? d_xB : d_xA;
    float*       xout = cur ? d_xA : d_xB;
    const float* c = d_C + v * CC;
    float r = sigf(c[d]        + bih[d]        + c[192 + d] + bhh[d]);
    float z = sigf(c[64 + d]   + bih[64 + d]   + c[256 + d] + bhh[64 + d]);
    float hn = c[320 + d] + bhh[128 + d];
    float n = tanhf(c[128 + d] + bih[128 + d] + r * hn);
    xout[idx] = (1.0f - z) * n + z * xin[idx];
}

// ---------------- pooling + MLP ----------------
__global__ void k_pool(int cur, const int* __restrict__ batch, int N) {
    int idx = blockIdx.x * blockDim.x + threadIdx.x;
    if (idx >= N * D) return;
    int v = idx >> 6, d = idx & 63;
    const float* x = cur ? d_xB : d_xA;
    atomicAdd(&d_pool[batch[v] * D + d], x[idx]);
}

__global__ void k_mlp(const float* __restrict__ w1, const float* __restrict__ b1,
                      const float* __restrict__ w2, const float* __restrict__ b2,
                      const float* __restrict__ w3, const float* __restrict__ b3,
                      float* __restrict__ out) {
    __shared__ float h1[32], h2[16];
    int g = blockIdx.x, t = threadIdx.x;
    if (t < 32) {
        float s = b1[t];
        for (int k = 0; k < D; k++) s += d_pool[g * D + k] * w1[t * D + k];
        h1[t] = (s > 0.0f) ? s : expm1f(s);
    }
    __syncthreads();
    if (t < 16) {
        float s = b2[t];
        for (int k = 0; k < 32; k++) s += h1[k] * w2[t * 32 + k];
        h2[t] = (s > 0.0f) ? s : expm1f(s);
    }
    __syncthreads();
    if (t == 0) {
        float s = b3[0];
        for (int k = 0; k < 16; k++) s += h2[k] * w3[k];
        out[g] = s;
    }
}

// ---------------- launch ----------------
extern "C" void kernel_launch(void* const* d_in, const int* in_sizes, int n_in,
                              void* d_out, int out_size) {
    const float* convw = (const float*)d_in[0];
    const float* wih   = (const float*)d_in[1];
    const float* whh   = (const float*)d_in[2];
    const float* bih   = (const float*)d_in[3];
    const float* bhh   = (const float*)d_in[4];
    const float* fc1w  = (const float*)d_in[5];
    const float* fc1b  = (const float*)d_in[6];
    const float* fc2w  = (const float*)d_in[7];
    const float* fc2b  = (const float*)d_in[8];
    const float* fc3w  = (const float*)d_in[9];
    const float* fc3b  = (const float*)d_in[10];
    const int*   ei    = (const int*)d_in[11];
    const int*   batch = (const int*)d_in[12];

    int E = in_sizes[11] / 2;
    int N = in_sizes[12];
    int G = out_size;
    float* out = (float*)d_out;

    int tb = 256;
    int gInit  = (max(N, 64 * D) + tb - 1) / tb;
    int gE     = (E + tb - 1) / tb;
    int gND    = (N * D + tb - 1) / tb;
    int gWarp  = (N * 32 + tb - 1) / tb;

    // CSR build
    k_init<<<gInit, tb>>>(N);
    k_count<<<gE, tb>>>(ei, E);
    k_scan<<<1, 1024>>>(N);
    k_fill<<<gE, tb>>>(ei, E);

    // analytic layers 1+2
    k_const<<<1, 192>>>(convw, wih, whh, bih, bhh);
    k_layer2<<<gND, tb>>>(bih + C3, N);           // writes d_xA (cur=0)
    k_bcat<<<(3 * D * CC + tb - 1) / tb, tb>>>(convw, wih, whh);

    // layers 3..5 (global layer index lg = l+2), ping-pong buffers
    int cur = 0;
    for (int l = 0; l < 3; l++) {
        int lg = l + 2;
        k_gather<<<gWarp, tb>>>(cur, N);
        k_gemm<<<148, 256>>>(cur, l, N);
        k_gru<<<gND, tb>>>(cur, bih + lg * C3, bhh + lg * C3, N);
        cur ^= 1;
    }

    // pooling + MLP head
    k_pool<<<gND, tb>>>(cur, batch, N);
    k_mlp<<<G, 64>>>(fc1w, fc1b, fc2w, fc2b, fc3w, fc3b, out);
}

// round 6
// speedup vs baseline: 1.3035x; 1.3035x over previous
#include <cuda_runtime.h>
#include <math.h>

#define D   64
#define C3  192
#define CC  384
#define MAXN 100352
#define MAXE 1600064

typedef unsigned long long ull;

// ---------------- device scratch (static, no allocation) ----------------
__device__ float d_xA[MAXN * D];
__device__ float d_xB[MAXN * D];
__device__ float d_S [MAXN * D];
__device__ int   d_indeg[MAXN];
__device__ int   d_off  [MAXN];
__device__ int   d_cur  [MAXN];
__device__ int   d_csrc [MAXE];
// per layer l=0..2 (global 2..4): permuted B, plain floats:
// Bf[l][k*384 + p], p = d*6 + gate; gate 0..2 = (W@Wih^T) r,z,n (uses S); 3..5 = Whh^T r,z,n (uses x)
__device__ __align__(16) float d_Bf[3][D * CC];
__device__ float d_q[C3], d_p2[C3], d_x1row[D];
__device__ float d_pool[64 * D];
__device__ int   d_gstart[66];

__device__ __forceinline__ float sigf(float x) { return 1.0f / (1.0f + expf(-x)); }

__device__ __forceinline__ void fma2(ull& d, ull a, ull b) {
    asm("fma.rn.f32x2 %0, %1, %2, %0;" : "+l"(d) : "l"(a), "l"(b));
}
__device__ __forceinline__ void unpk(float& lo, float& hi, ull v) {
    asm("mov.b64 {%0,%1}, %2;" : "=f"(lo), "=f"(hi) : "l"(v));
}
__device__ __forceinline__ ull dup(float v) {
    ull d;
    asm("mov.b64 %0, {%1,%1};" : "=l"(d) : "f"(v));
    return d;
}

// ---------------- CSR build ----------------
__global__ void k_init(int N, int G) {
    int i = blockIdx.x * blockDim.x + threadIdx.x;
    if (i < N) d_indeg[i] = 0;
    if (i <= G + 1) d_gstart[i] = N;
}

__global__ void k_count(const int* __restrict__ ei, int E) {
    int i = blockIdx.x * blockDim.x + threadIdx.x;
    if (i < E) atomicAdd(&d_indeg[ei[E + i]], 1);
}

__global__ void k_scan(int N) {
    __shared__ int sm[1024];
    int t = threadIdx.x;
    int chunk = (N + 1023) >> 10;
    int b = t * chunk, e = min(N, b + chunk);
    int s = 0;
    for (int i = b; i < e; i++) s += d_indeg[i];
    sm[t] = s;
    __syncthreads();
    for (int off = 1; off < 1024; off <<= 1) {
        int v = (t >= off) ? sm[t - off] : 0;
        __syncthreads();
        sm[t] += v;
        __syncthreads();
    }
    int run = sm[t] - s;
    for (int i = b; i < e; i++) {
        d_off[i] = run;
        d_cur[i] = run;
        run += d_indeg[i];
    }
}

__global__ void k_fill(const int* __restrict__ ei, int E) {
    int i = blockIdx.x * blockDim.x + threadIdx.x;
    if (i < E) {
        int s = ei[i];
        int d = ei[E + i];
        int p = atomicAdd(&d_cur[d], 1);
        d_csrc[p] = s;
    }
}

// ---------------- layers 1+2 analytic shortcuts ----------------
__global__ void k_const(const float* __restrict__ convw,
                        const float* __restrict__ wih,
                        const float* __restrict__ whh,
                        const float* __restrict__ bih,
                        const float* __restrict__ bhh) {
    __shared__ float x1[D], m2[D];
    int t = threadIdx.x;
    if (t < D) {
        float r = sigf(bih[t] + bhh[t]);
        float z = sigf(bih[64 + t] + bhh[64 + t]);
        float n = tanhf(bih[128 + t] + r * bhh[128 + t]);
        x1[t] = (1.0f - z) * n;
    }
    __syncthreads();
    if (t < D) {
        const float* w1 = convw + 1 * D * D;
        float s = 0.0f;
        for (int k = 0; k < D; k++) s += x1[k] * w1[k * D + t];
        m2[t] = s;
        d_x1row[t] = x1[t];
    }
    __syncthreads();
    if (t < C3) {
        const float* wih1 = wih + 1 * C3 * D;
        const float* whh1 = whh + 1 * C3 * D;
        const float* bhh1 = bhh + 1 * C3;
        float sq = 0.0f, sp = 0.0f;
        for (int j = 0; j < D; j++) {
            sq += m2[j] * wih1[t * D + j];
            sp += x1[j] * whh1[t * D + j];
        }
        d_q[t]  = sq;
        d_p2[t] = sp + bhh1[t];
    }
}

__global__ void k_layer2(const float* __restrict__ bih1, int N) {
    int idx = blockIdx.x * blockDim.x + threadIdx.x;
    if (idx >= N * D) return;
    int v = idx >> 6, d = idx & 63;
    float deg = (float)d_indeg[v];
    float r = sigf(deg * d_q[d]       + bih1[d]       + d_p2[d]);
    float z = sigf(deg * d_q[64 + d]  + bih1[64 + d]  + d_p2[64 + d]);
    float n = tanhf(deg * d_q[128 + d] + bih1[128 + d] + r * d_p2[128 + d]);
    d_xA[idx] = (1.0f - z) * n + z * d_x1row[d];
}

// ---------------- precompute permuted Bf for layers 2..4 ----------------
__global__ void k_bcat(const float* __restrict__ convw,
                       const float* __restrict__ wih,
                       const float* __restrict__ whh) {
    int idx = blockIdx.x * blockDim.x + threadIdx.x;
    if (idx >= 3 * D * CC) return;
    int l0 = idx / (D * CC);
    int rem = idx - l0 * (D * CC);
    int k = rem / CC;
    int p = rem - k * CC;
    int d = p / 6, g = p % 6;
    int lg = l0 + 2;
    float val;
    if (g < 3) {
        const float* w  = convw + lg * D * D;
        const float* wi = wih   + lg * C3 * D + (g * 64 + d) * D;
        float s = 0.0f;
        for (int j = 0; j < D; j++) s += w[k * D + j] * wi[j];
        val = s;
    } else {
        val = whh[lg * C3 * D + ((g - 3) * 64 + d) * D + k];
    }
    d_Bf[l0][k * CC + p] = val;
}

// ---------------- gather: S[v] = sum_{u in in(v)} x[u] ----------------
__global__ void k_gather(int cur, int N) {
    int w = (blockIdx.x * blockDim.x + threadIdx.x) >> 5;
    int lane = threadIdx.x & 31;
    if (w >= N) return;
    const float* x = cur ? d_xB : d_xA;
    int o = d_off[w], dg = d_indeg[w];
    float2 acc = make_float2(0.0f, 0.0f);
    for (int e = 0; e < dg; e++) {
        int u = d_csrc[o + e];
        float2 v = ((const float2*)(x + u * D))[lane];
        acc.x += v.x;
        acc.y += v.y;
    }
    ((float2*)(d_S + w * D))[lane] = acc;
}

// ---------------- fused GEMM + GRU ----------------
// 256 threads = 8 node-groups(ty) x 32 lanes(cx). Thread tile: 8 nodes (4 f32x2
// node-pairs) x 12 cols = feature dims {2cx,2cx+1} x 6 gates.
// smem transposed: sS[k][n], sX[k][n], pad 72.
__global__ void __launch_bounds__(256) k_gemm_gru(int cur, int l, int N,
                                                  const float* __restrict__ bih,
                                                  const float* __restrict__ bhh) {
    __shared__ float sS[64 * 72];
    __shared__ float sX[64 * 72];
    const float* Xin  = cur ? d_xB : d_xA;
    float*       Xout = cur ? d_xA : d_xB;
    const float* __restrict__ Bf = d_Bf[l];

    int ty = threadIdx.x >> 5;
    int cx = threadIdx.x & 31;
    int nb = ty * 8;
    int d0 = 2 * cx, d1 = 2 * cx + 1;

    float bir0 = __ldg(&bih[d0]),        bir1 = __ldg(&bih[d1]);
    float biz0 = __ldg(&bih[64 + d0]),   biz1 = __ldg(&bih[64 + d1]);
    float bin0 = __ldg(&bih[128 + d0]),  bin1 = __ldg(&bih[128 + d1]);
    float bhr0 = __ldg(&bhh[d0]),        bhr1 = __ldg(&bhh[d1]);
    float bhz0 = __ldg(&bhh[64 + d0]),   bhz1 = __ldg(&bhh[64 + d1]);
    float bhn0 = __ldg(&bhh[128 + d0]),  bhn1 = __ldg(&bhh[128 + d1]);

    int ntiles = (N + 63) >> 6;
    for (int tile = blockIdx.x; tile < ntiles; tile += gridDim.x) {
        int n0 = tile << 6;
        __syncthreads();
        // stage transposed: 64 nodes x 16 float4 = 1024 items; each item loads S AND x
        for (int i = threadIdx.x; i < 1024; i += 256) {
            int q = i >> 6;            // 0..15  (float4 index within row)
            int n = i & 63;            // node within tile
            int gn = n0 + n;
            float4 vs = make_float4(0.f, 0.f, 0.f, 0.f);
            float4 vx = make_float4(0.f, 0.f, 0.f, 0.f);
            if (gn < N) {
                vs = ((const float4*)d_S)[gn * 16 + q];
                vx = ((const float4*)Xin)[gn * 16 + q];
            }
            int kb = q * 4;
            sS[(kb + 0) * 72 + n] = vs.x; sS[(kb + 1) * 72 + n] = vs.y;
            sS[(kb + 2) * 72 + n] = vs.z; sS[(kb + 3) * 72 + n] = vs.w;
            sX[(kb + 0) * 72 + n] = vx.x; sX[(kb + 1) * 72 + n] = vx.y;
            sX[(kb + 2) * 72 + n] = vx.z; sX[(kb + 3) * 72 + n] = vx.w;
        }
        __syncthreads();

        ull acc[4][12];
        #pragma unroll
        for (int i = 0; i < 4; i++)
            #pragma unroll
            for (int j = 0; j < 12; j++) acc[i][j] = 0ull;

        const float4* b4base = (const float4*)(Bf + 12 * cx);

        #pragma unroll 4
        for (int k = 0; k < 64; k++) {
            ull s[4], x[4];
            #pragma unroll
            for (int i = 0; i < 4; i++) {
                s[i] = *(const ull*)&sS[k * 72 + nb + 2 * i];
                x[i] = *(const ull*)&sX[k * 72 + nb + 2 * i];
            }
            // 12 un-duplicated B scalars -> register-dup pairs
            const float4* b4 = (const float4*)((const float*)b4base + k * CC);
            float4 v0 = __ldg(&b4[0]);
            float4 v1 = __ldg(&b4[1]);
            float4 v2 = __ldg(&b4[2]);
            ull b[12];
            b[0]  = dup(v0.x); b[1]  = dup(v0.y); b[2]  = dup(v0.z); b[3]  = dup(v0.w);
            b[4]  = dup(v1.x); b[5]  = dup(v1.y); b[6]  = dup(v1.z); b[7]  = dup(v1.w);
            b[8]  = dup(v2.x); b[9]  = dup(v2.y); b[10] = dup(v2.z); b[11] = dup(v2.w);
            #pragma unroll
            for (int i = 0; i < 4; i++) {
                #pragma unroll
                for (int j = 0; j < 12; j++) {
                    fma2(acc[i][j], (j % 6 < 3) ? s[i] : x[i], b[j]);
                }
            }
        }

        // epilogue: GRU per node; xin via coalesced global (L1-hot), store float2
        #pragma unroll
        for (int i = 0; i < 4; i++) {
            float g[12][2];
            #pragma unroll
            for (int j = 0; j < 12; j++) unpk(g[j][0], g[j][1], acc[i][j]);
            #pragma unroll
            for (int sel = 0; sel < 2; sel++) {
                int n = n0 + nb + 2 * i + sel;
                if (n < N) {
                    float2 xi = __ldg(((const float2*)(Xin + n * D)) + cx);
                    float r0 = sigf(g[0][sel] + bir0 + g[3][sel] + bhr0);
                    float z0 = sigf(g[1][sel] + biz0 + g[4][sel] + bhz0);
                    float nn0 = tanhf(g[2][sel] + bin0 + r0 * (g[5][sel] + bhn0));
                    float o0 = (1.0f - z0) * nn0 + z0 * xi.x;
                    float r1 = sigf(g[6][sel] + bir1 + g[9][sel] + bhr1);
                    float z1 = sigf(g[7][sel] + biz1 + g[10][sel] + bhz1);
                    float nn1 = tanhf(g[8][sel] + bin1 + r1 * (g[11][sel] + bhn1));
                    float o1 = (1.0f - z1) * nn1 + z1 * xi.y;
                    ((float2*)(Xout + n * D))[cx] = make_float2(o0, o1);
                }
            }
        }
    }
}

// ---------------- segmented pooling (batch is sorted) ----------------
__global__ void k_gstart(const int* __restrict__ batch, int N) {
    int i = blockIdx.x * blockDim.x + threadIdx.x;
    if (i < N) atomicMin(&d_gstart[batch[i]], i);
}

__global__ void k_gfix(int G, int N) {
    d_gstart[G] = N;
    for (int g = G - 1; g >= 0; g--)
        if (d_gstart[g] > d_gstart[g + 1]) d_gstart[g] = d_gstart[g + 1];
}

__global__ void k_pool2(int cur, int N) {
    __shared__ float red[256];
    const float* x = cur ? d_xB : d_xA;
    int g = blockIdx.x;
    int t = threadIdx.x;
    int d = t & 63, part = t >> 6;
    int s = d_gstart[g], e = d_gstart[g + 1];
    float acc = 0.0f;
    for (int n = s + part; n < e; n += 4) acc += x[n * D + d];
    red[t] = acc;
    __syncthreads();
    if (t < 64)
        d_pool[g * D + t] = red[t] + red[64 + t] + red[128 + t] + red[192 + t];
}

__global__ void k_mlp(const float* __restrict__ w1, const float* __restrict__ b1,
                      const float* __restrict__ w2, const float* __restrict__ b2,
                      const float* __restrict__ w3, const float* __restrict__ b3,
                      float* __restrict__ out) {
    __shared__ float h1[32], h2[16];
    int g = blockIdx.x, t = threadIdx.x;
    if (t < 32) {
        float s = b1[t];
        for (int k = 0; k < D; k++) s += d_pool[g * D + k] * w1[t * D + k];
        h1[t] = (s > 0.0f) ? s : expm1f(s);
    }
    __syncthreads();
    if (t < 16) {
        float s = b2[t];
        for (int k = 0; k < 32; k++) s += h1[k] * w2[t * 32 + k];
        h2[t] = (s > 0.0f) ? s : expm1f(s);
    }
    __syncthreads();
    if (t == 0) {
        float s = b3[0];
        for (int k = 0; k < 16; k++) s += h2[k] * w3[k];
        out[g] = s;
    }
}

// ---------------- launch ----------------
extern "C" void kernel_launch(void* const* d_in, const int* in_sizes, int n_in,
                              void* d_out, int out_size) {
    const float* convw = (const float*)d_in[0];
    const float* wih   = (const float*)d_in[1];
    const float* whh   = (const float*)d_in[2];
    const float* bih   = (const float*)d_in[3];
    const float* bhh   = (const float*)d_in[4];
    const float* fc1w  = (const float*)d_in[5];
    const float* fc1b  = (const float*)d_in[6];
    const float* fc2w  = (const float*)d_in[7];
    const float* fc2b  = (const float*)d_in[8];
    const float* fc3w  = (const float*)d_in[9];
    const float* fc3b  = (const float*)d_in[10];
    const int*   ei    = (const int*)d_in[11];
    const int*   batch = (const int*)d_in[12];

    int E = in_sizes[11] / 2;
    int N = in_sizes[12];
    int G = out_size;
    float* out = (float*)d_out;

    int tb = 256;
    int gN    = (N + tb - 1) / tb;
    int gE    = (E + tb - 1) / tb;
    int gND   = (N * D + tb - 1) / tb;
    int gWarp = (N * 32 + tb - 1) / tb;

    // CSR build + graph ranges
    k_init<<<gN, tb>>>(N, G);
    k_count<<<gE, tb>>>(ei, E);
    k_scan<<<1, 1024>>>(N);
    k_fill<<<gE, tb>>>(ei, E);
    k_gstart<<<gN, tb>>>(batch, N);
    k_gfix<<<1, 1>>>(G, N);

    // analytic layers 1+2
    k_const<<<1, 192>>>(convw, wih, whh, bih, bhh);
    k_layer2<<<gND, tb>>>(bih + C3, N);           // writes d_xA (cur=0)
    k_bcat<<<(3 * D * CC + tb - 1) / tb, tb>>>(convw, wih, whh);

    // layers 3..5 fused GEMM+GRU, ping-pong
    int cur = 0;
    for (int l = 0; l < 3; l++) {
        int lg = l + 2;
        k_gather<<<gWarp, tb>>>(cur, N);
        k_gemm_gru<<<148, 256>>>(cur, l, N, bih + lg * C3, bhh + lg * C3);
        cur ^= 1;
    }

    // pooling + MLP head
    k_pool2<<<G, 256>>>(cur, N);
    k_mlp<<<G, 64>>>(fc1w, fc1b, fc2w, fc2b, fc3w, fc3b, out);
}

// round 8
// speedup vs baseline: 1.5856x; 1.2165x over previous
#include <cuda_runtime.h>
#include <cuda_bf16.h>
#include <math.h>
#include <stdint.h>

#define D   64
#define C3  192
#define MAXN 100352
#define MAXE 1600064

// ---------------- device scratch (static, no allocation) ----------------
__device__ float d_xA[MAXN * D];
__device__ float d_xB[MAXN * D];
__device__ float d_S [MAXN * D];
__device__ int   d_indeg[MAXN];
__device__ int   d_off  [MAXN];
__device__ int   d_cur  [MAXN];
__device__ int   d_csrc [MAXE];
// Packed B per layer l=0..2 (global 2..4): [hi/lo][k=0..63][col=0..383] bf16
// cols 0..191 = gi weights (convW @ Wih^T), cols 192..383 = gh weights (Whh)
__device__ __align__(16) __nv_bfloat16 d_Bk[3][2][64][384];
__device__ float d_q[C3], d_p2[C3], d_x1row[D];
__device__ float d_pool[64 * D];
__device__ int   d_gstart[66];

__device__ __forceinline__ float sigf(float x) { return 1.0f / (1.0f + expf(-x)); }

__device__ __forceinline__ uint32_t smem_u32(const void* p) {
    uint32_t a;
    asm("{ .reg .u64 t; cvta.to.shared.u64 t, %1; cvt.u32.u64 %0, t; }" : "=r"(a) : "l"(p));
    return a;
}
__device__ __forceinline__ void ldmA4(uint32_t a[4], uint32_t addr) {
    asm volatile("ldmatrix.sync.aligned.m8n8.x4.shared.b16 {%0,%1,%2,%3}, [%4];"
                 : "=r"(a[0]), "=r"(a[1]), "=r"(a[2]), "=r"(a[3]) : "r"(addr));
}
__device__ __forceinline__ void ldmB2(uint32_t b[2], uint32_t addr) {
    asm volatile("ldmatrix.sync.aligned.m8n8.x2.trans.shared.b16 {%0,%1}, [%2];"
                 : "=r"(b[0]), "=r"(b[1]) : "r"(addr));
}
__device__ __forceinline__ void mma16816(float c[4], const uint32_t a[4], const uint32_t b[2]) {
    asm volatile("mma.sync.aligned.m16n8k16.row.col.f32.bf16.bf16.f32 "
                 "{%0,%1,%2,%3}, {%4,%5,%6,%7}, {%8,%9}, {%0,%1,%2,%3};"
                 : "+f"(c[0]), "+f"(c[1]), "+f"(c[2]), "+f"(c[3])
                 : "r"(a[0]), "r"(a[1]), "r"(a[2]), "r"(a[3]), "r"(b[0]), "r"(b[1]));
}

// ---------------- CSR build ----------------
__global__ void k_init(int N, int G) {
    int i = blockIdx.x * blockDim.x + threadIdx.x;
    if (i < N) d_indeg[i] = 0;
    if (i <= G + 1) d_gstart[i] = N;
}

__global__ void k_count(const int* __restrict__ ei, int E) {
    int i = blockIdx.x * blockDim.x + threadIdx.x;
    if (i < E) atomicAdd(&d_indeg[ei[E + i]], 1);
}

__global__ void k_scan(int N) {
    __shared__ int sm[1024];
    int t = threadIdx.x;
    int chunk = (N + 1023) >> 10;
    int b = t * chunk, e = min(N, b + chunk);
    int s = 0;
    for (int i = b; i < e; i++) s += d_indeg[i];
    sm[t] = s;
    __syncthreads();
    for (int off = 1; off < 1024; off <<= 1) {
        int v = (t >= off) ? sm[t - off] : 0;
        __syncthreads();
        sm[t] += v;
        __syncthreads();
    }
    int run = sm[t] - s;
    for (int i = b; i < e; i++) {
        d_off[i] = run;
        d_cur[i] = run;
        run += d_indeg[i];
    }
}

__global__ void k_fill(const int* __restrict__ ei, int E) {
    int i = blockIdx.x * blockDim.x + threadIdx.x;
    if (i < E) {
        int s = ei[i];
        int d = ei[E + i];
        int p = atomicAdd(&d_cur[d], 1);
        d_csrc[p] = s;
    }
}

// ---------------- layers 1+2 analytic shortcuts ----------------
__global__ void k_const(const float* __restrict__ convw,
                        const float* __restrict__ wih,
                        const float* __restrict__ whh,
                        const float* __restrict__ bih,
                        const float* __restrict__ bhh) {
    __shared__ float x1[D], m2[D];
    int t = threadIdx.x;
    if (t < D) {
        float r = sigf(bih[t] + bhh[t]);
        float z = sigf(bih[64 + t] + bhh[64 + t]);
        float n = tanhf(bih[128 + t] + r * bhh[128 + t]);
        x1[t] = (1.0f - z) * n;
    }
    __syncthreads();
    if (t < D) {
        const float* w1 = convw + 1 * D * D;
        float s = 0.0f;
        for (int k = 0; k < D; k++) s += x1[k] * w1[k * D + t];
        m2[t] = s;
        d_x1row[t] = x1[t];
    }
    __syncthreads();
    if (t < C3) {
        const float* wih1 = wih + 1 * C3 * D;
        const float* whh1 = whh + 1 * C3 * D;
        const float* bhh1 = bhh + 1 * C3;
        float sq = 0.0f, sp = 0.0f;
        for (int j = 0; j < D; j++) {
            sq += m2[j] * wih1[t * D + j];
            sp += x1[j] * whh1[t * D + j];
        }
        d_q[t]  = sq;
        d_p2[t] = sp + bhh1[t];
    }
}

__global__ void k_layer2(const float* __restrict__ bih1, int N) {
    int idx = blockIdx.x * blockDim.x + threadIdx.x;
    if (idx >= N * D) return;
    int v = idx >> 6, d = idx & 63;
    float deg = (float)d_indeg[v];
    float r = sigf(deg * d_q[d]       + bih1[d]       + d_p2[d]);
    float z = sigf(deg * d_q[64 + d]  + bih1[64 + d]  + d_p2[64 + d]);
    float n = tanhf(deg * d_q[128 + d] + bih1[128 + d] + r * d_p2[128 + d]);
    d_xA[idx] = (1.0f - z) * n + z * d_x1row[d];
}

// ---------------- pre-pack bf16 hi/lo B blocks [k][col] ----------------
__global__ void k_bprep(const float* __restrict__ convw,
                        const float* __restrict__ wih,
                        const float* __restrict__ whh) {
    int idx = blockIdx.x * blockDim.x + threadIdx.x;  // 3*2*192*64
    if (idx >= 73728) return;
    int l0 = idx / 24576;
    int rem = idx % 24576;
    int m = rem / 12288;
    int rem2 = rem % 12288;
    int c = rem2 >> 6;      // 0..191 (gate*64 + d)
    int k = rem2 & 63;
    int lg = l0 + 2;
    float val;
    if (m == 0) {
        const float* w  = convw + lg * D * D + k * D;
        const float* wi = wih   + lg * C3 * D + c * D;
        float s = 0.0f;
        for (int j = 0; j < D; j++) s += w[j] * wi[j];
        val = s;
    } else {
        val = whh[lg * C3 * D + c * D + k];
    }
    __nv_bfloat16 hi = __float2bfloat16(val);
    __nv_bfloat16 lo = __float2bfloat16(val - __bfloat162float(hi));
    int col = m * 192 + c;
    d_Bk[l0][0][k][col] = hi;
    d_Bk[l0][1][k][col] = lo;
}

// ---------------- gather: S[v] = sum_{u in in(v)} x[u] ----------------
__global__ void k_gather(int cur, int N) {
    int w = (blockIdx.x * blockDim.x + threadIdx.x) >> 5;
    int lane = threadIdx.x & 31;
    if (w >= N) return;
    const float* x = cur ? d_xB : d_xA;
    int o = d_off[w], dg = d_indeg[w];
    float2 acc = make_float2(0.0f, 0.0f);
    for (int e = 0; e < dg; e++) {
        int u = d_csrc[o + e];
        float2 v = ((const float2*)(x + u * D))[lane];
        acc.x += v.x;
        acc.y += v.y;
    }
    ((float2*)(d_S + w * D))[lane] = acc;
}

// ---------------- HMMA fused GEMM + GRU ----------------
// 256 threads, persistent. Tile = 128 nodes. B resident in smem.
// Warps 0-3: gi cols 0..191 (A = S); warps 4-7: gh cols 192..383 (A = X).
// 3-term bf16 split: Ah*Bh + Al*Bh + Ah*Bl.
#define BP 392            // B smem pitch (bf16 elems): 784B = 49*16B (odd -> no ldmatrix conflicts)
#define AP 72             // A smem pitch (bf16 elems): 144B = 9*16B (odd)
#define SM_BHI 0
#define SM_BLO 50176
#define SM_SHI 100352
#define SM_SLO 118784
#define SM_XHI 137216
#define SM_XLO 155648
#define SM_GATE 174080    // 32 x 392 fp32 = 50176
#define SM_TOT  224256
#define GP 392            // gate pitch in floats

__global__ void __launch_bounds__(256, 1) k_gemm_gru_mma(int cur, int l, int N,
                                                         const float* __restrict__ bih,
                                                         const float* __restrict__ bhh) {
    extern __shared__ char smem[];
    uint32_t sb = smem_u32(smem);
    float* sGate = (float*)(smem + SM_GATE);
    int tid = threadIdx.x, wid = tid >> 5, lane = tid & 31;
    const float* Xin  = cur ? d_xB : d_xA;
    float*       Xout = cur ? d_xA : d_xB;

    // ---- load resident B (hi/lo) with pitch BP ----
    {
        const int4* srcH = (const int4*)(&d_Bk[l][0][0][0]);
        const int4* srcL = (const int4*)(&d_Bk[l][1][0][0]);
        for (int i = tid; i < 3072; i += 256) {   // 3072 int4 = 24576 elems each
            int row = i / 48, cb = i % 48;        // 48 int4 per 384-col row
            *(int4*)(smem + SM_BHI + row * (BP * 2) + cb * 16) = srcH[i];
            *(int4*)(smem + SM_BLO + row * (BP * 2) + cb * 16) = srcL[i];
        }
    }
    __syncthreads();

    // per-thread ldmatrix lane offsets
    uint32_t aoff = (uint32_t)(lane & 15) * (AP * 2) + ((lane >> 4) << 3) * 2;
    uint32_t boff = (uint32_t)(lane & 15) * (BP * 2);
    int wcol = wid * 48;                         // global output col base for this warp
    uint32_t baseAhi = sb + ((wid < 4) ? SM_SHI : SM_XHI);
    uint32_t baseAlo = sb + ((wid < 4) ? SM_SLO : SM_XLO);
    int gID = lane >> 2, tig = lane & 3;

    int ntiles = (N + 127) >> 7;
    for (int tile = blockIdx.x; tile < ntiles; tile += gridDim.x) {
        int n0 = tile << 7;

        // ---- stage A: fp32 S|X -> bf16 hi/lo ----
        for (int i = tid; i < 4096; i += 256) {   // 128 nodes x 32 float2
            int node = i >> 5, kp = i & 31;
            int gn = n0 + node;
            float2 s = make_float2(0.f, 0.f), x = make_float2(0.f, 0.f);
            if (gn < N) {
                s = __ldg((const float2*)(d_S + gn * 64) + kp);
                x = __ldg((const float2*)(Xin + gn * 64) + kp);
            }
            __nv_bfloat162 sh = __float22bfloat162_rn(s);
            float2 shf = __bfloat1622float2(sh);
            __nv_bfloat162 sl = __float22bfloat162_rn(make_float2(s.x - shf.x, s.y - shf.y));
            __nv_bfloat162 xh = __float22bfloat162_rn(x);
            float2 xhf = __bfloat1622float2(xh);
            __nv_bfloat162 xl = __float22bfloat162_rn(make_float2(x.x - xhf.x, x.y - xhf.y));
            uint32_t off = (uint32_t)node * (AP * 2) + kp * 4;
            *(uint32_t*)(smem + SM_SHI + off) = *(uint32_t*)&sh;
            *(uint32_t*)(smem + SM_SLO + off) = *(uint32_t*)&sl;
            *(uint32_t*)(smem + SM_XHI + off) = *(uint32_t*)&xh;
            *(uint32_t*)(smem + SM_XLO + off) = *(uint32_t*)&xl;
        }
        __syncthreads();

        for (int mc = 0; mc < 4; mc++) {
            int m0 = mc * 32;

            float c[2][6][4];
            #pragma unroll
            for (int mf = 0; mf < 2; mf++)
                #pragma unroll
                for (int j = 0; j < 6; j++)
                    #pragma unroll
                    for (int q = 0; q < 4; q++) c[mf][j][q] = 0.0f;

            #pragma unroll
            for (int ks = 0; ks < 4; ks++) {
                int k0 = ks * 16;
                uint32_t ah[2][4], al[2][4];
                uint32_t abase = (uint32_t)m0 * (AP * 2) + k0 * 2 + aoff;
                ldmA4(ah[0], baseAhi + abase);
                ldmA4(ah[1], baseAhi + abase + 16 * (AP * 2));
                ldmA4(al[0], baseAlo + abase);
                ldmA4(al[1], baseAlo + abase + 16 * (AP * 2));
                #pragma unroll
                for (int j = 0; j < 6; j++) {
                    uint32_t bh[2], bl[2];
                    uint32_t bbase = (uint32_t)k0 * (BP * 2) + (wcol + 8 * j) * 2 + boff;
                    ldmB2(bh, sb + SM_BHI + bbase);
                    ldmB2(bl, sb + SM_BLO + bbase);
                    mma16816(c[0][j], ah[0], bh);
                    mma16816(c[1][j], ah[1], bh);
                    mma16816(c[0][j], al[0], bh);
                    mma16816(c[1][j], al[1], bh);
                    mma16816(c[0][j], ah[0], bl);
                    mma16816(c[1][j], ah[1], bl);
                }
            }

            // write accums to gate buffer
            #pragma unroll
            for (int mf = 0; mf < 2; mf++) {
                int row0 = mf * 16 + gID;
                #pragma unroll
                for (int j = 0; j < 6; j++) {
                    int col = wcol + 8 * j + 2 * tig;
                    *(float2*)(sGate + row0 * GP + col)       = make_float2(c[mf][j][0], c[mf][j][1]);
                    *(float2*)(sGate + (row0 + 8) * GP + col) = make_float2(c[mf][j][2], c[mf][j][3]);
                }
            }
            __syncthreads();

            // fused GRU: thread -> (row r = tid>>3, dims d0..d0+7)
            {
                int r = tid >> 3;
                int d0 = (tid & 7) * 8;
                int node = n0 + m0 + r;
                if (node < N) {
                    const float* gr = sGate + r * GP;
                    float ov[8];
                    const float* xr = Xin + node * 64 + d0;
                    float4 xa = __ldg((const float4*)xr);
                    float4 xb = __ldg((const float4*)xr + 1);
                    float xiv[8] = {xa.x, xa.y, xa.z, xa.w, xb.x, xb.y, xb.z, xb.w};
                    #pragma unroll
                    for (int jj = 0; jj < 8; jj++) {
                        int d = d0 + jj;
                        float rr = sigf(gr[d]       + bih[d]       + gr[192 + d] + bhh[d]);
                        float zz = sigf(gr[64 + d]  + bih[64 + d]  + gr[256 + d] + bhh[64 + d]);
                        float nn = tanhf(gr[128 + d] + bih[128 + d] +
                                         rr * (gr[320 + d] + bhh[128 + d]));
                        ov[jj] = (1.0f - zz) * nn + zz * xiv[jj];
                    }
                    float* xo = Xout + node * 64 + d0;
                    ((float4*)xo)[0] = make_float4(ov[0], ov[1], ov[2], ov[3]);
                    ((float4*)xo)[1] = make_float4(ov[4], ov[5], ov[6], ov[7]);
                }
            }
            __syncthreads();
        }
    }
}

// ---------------- segmented pooling (batch is sorted) ----------------
__global__ void k_gstart(const int* __restrict__ batch, int N) {
    int i = blockIdx.x * blockDim.x + threadIdx.x;
    if (i < N) atomicMin(&d_gstart[batch[i]], i);
}

__global__ void k_gfix(int G, int N) {
    d_gstart[G] = N;
    for (int g = G - 1; g >= 0; g--)
        if (d_gstart[g] > d_gstart[g + 1]) d_gstart[g] = d_gstart[g + 1];
}

__global__ void k_pool2(int cur, int N) {
    __shared__ float red[256];
    const float* x = cur ? d_xB : d_xA;
    int g = blockIdx.x;
    int t = threadIdx.x;
    int d = t & 63, part = t >> 6;
    int s = d_gstart[g], e = d_gstart[g + 1];
    float acc = 0.0f;
    for (int n = s + part; n < e; n += 4) acc += x[n * D + d];
    red[t] = acc;
    __syncthreads();
    if (t < 64)
        d_pool[g * D + t] = red[t] + red[64 + t] + red[128 + t] + red[192 + t];
}

__global__ void k_mlp(const float* __restrict__ w1, const float* __restrict__ b1,
                      const float* __restrict__ w2, const float* __restrict__ b2,
                      const float* __restrict__ w3, const float* __restrict__ b3,
                      float* __restrict__ out) {
    __shared__ float h1[32], h2[16];
    int g = blockIdx.x, t = threadIdx.x;
    if (t < 32) {
        float s = b1[t];
        for (int k = 0; k < D; k++) s += d_pool[g * D + k] * w1[t * D + k];
        h1[t] = (s > 0.0f) ? s : expm1f(s);
    }
    __syncthreads();
    if (t < 16) {
        float s = b2[t];
        for (int k = 0; k < 32; k++) s += h1[k] * w2[t * 32 + k];
        h2[t] = (s > 0.0f) ? s : expm1f(s);
    }
    __syncthreads();
    if (t == 0) {
        float s = b3[0];
        for (int k = 0; k < 16; k++) s += h2[k] * w3[k];
        out[g] = s;
    }
}

// ---------------- launch ----------------
extern "C" void kernel_launch(void* const* d_in, const int* in_sizes, int n_in,
                              void* d_out, int out_size) {
    const float* convw = (const float*)d_in[0];
    const float* wih   = (const float*)d_in[1];
    const float* whh   = (const float*)d_in[2];
    const float* bih   = (const float*)d_in[3];
    const float* bhh   = (const float*)d_in[4];
    const float* fc1w  = (const float*)d_in[5];
    const float* fc1b  = (const float*)d_in[6];
    const float* fc2w  = (const float*)d_in[7];
    const float* fc2b  = (const float*)d_in[8];
    const float* fc3w  = (const float*)d_in[9];
    const float* fc3b  = (const float*)d_in[10];
    const int*   ei    = (const int*)d_in[11];
    const int*   batch = (const int*)d_in[12];

    int E = in_sizes[11] / 2;
    int N = in_sizes[12];
    int G = out_size;
    float* out = (float*)d_out;

    static int smem_set = 0;
    if (!smem_set) {
        cudaFuncSetAttribute(k_gemm_gru_mma, cudaFuncAttributeMaxDynamicSharedMemorySize, SM_TOT);
        smem_set = 1;
    }

    int tb = 256;
    int gN    = (N + tb - 1) / tb;
    int gE    = (E + tb - 1) / tb;
    int gND   = (N * D + tb - 1) / tb;
    int gWarp = (N * 32 + tb - 1) / tb;

    // CSR build + graph ranges
    k_init<<<gN, tb>>>(N, G);
    k_count<<<gE, tb>>>(ei, E);
    k_scan<<<1, 1024>>>(N);
    k_fill<<<gE, tb>>>(ei, E);
    k_gstart<<<gN, tb>>>(batch, N);
    k_gfix<<<1, 1>>>(G, N);

    // analytic layers 1+2 and B packing
    k_const<<<1, 192>>>(convw, wih, whh, bih, bhh);
    k_layer2<<<gND, tb>>>(bih + C3, N);           // writes d_xA (cur=0)
    k_bprep<<<(73728 + tb - 1) / tb, tb>>>(convw, wih, whh);

    // layers 3..5: gather + HMMA fused GEMM+GRU, ping-pong
    int cur = 0;
    for (int l = 0; l < 3; l++) {
        int lg = l + 2;
        k_gather<<<gWarp, tb>>>(cur, N);
        k_gemm_gru_mma<<<148, 256, SM_TOT>>>(cur, l, N, bih + lg * C3, bhh + lg * C3);
        cur ^= 1;
    }

    // pooling + MLP head
    k_pool2<<<G, 256>>>(cur, N);
    k_mlp<<<G, 64>>>(fc1w, fc1b, fc2w, fc2b, fc3w, fc3b, out);
}

// round 9
// speedup vs baseline: 1.6240x; 1.0242x over previous
#include <cuda_runtime.h>
#include <cuda_bf16.h>
#include <math.h>
#include <stdint.h>

#define D   64
#define C3  192
#define MAXN 100352
#define MAXE 1600064

// ---------------- device scratch (static, no allocation) ----------------
__device__ float d_xA[MAXN * D];
__device__ float d_xB[MAXN * D];
__device__ float d_S [MAXN * D];
__device__ int   d_indeg[MAXN];
__device__ int   d_off  [MAXN];
__device__ int   d_cur  [MAXN];
__device__ int   d_csrc [MAXE];
// Packed B per layer l=0..2 (global 2..4): [hi/lo][k=0..63][col'=0..383] bf16
// col' = w*48 + j*8 + t : warp w owns dims 8w..8w+7; j=0..2 gi gates (r,z,n), j=3..5 gh gates
__device__ __align__(16) __nv_bfloat16 d_Bk[3][2][64][384];
__device__ float d_q[C3], d_p2[C3], d_x1row[D];
__device__ float d_pool[64 * D];
__device__ int   d_gstart[66];

__device__ __forceinline__ float sigf(float x) { return 1.0f / (1.0f + expf(-x)); }

__device__ __forceinline__ uint32_t smem_u32(const void* p) {
    uint32_t a;
    asm("{ .reg .u64 t; cvta.to.shared.u64 t, %1; cvt.u32.u64 %0, t; }" : "=r"(a) : "l"(p));
    return a;
}
__device__ __forceinline__ void ldmA4(uint32_t a[4], uint32_t addr) {
    asm volatile("ldmatrix.sync.aligned.m8n8.x4.shared.b16 {%0,%1,%2,%3}, [%4];"
                 : "=r"(a[0]), "=r"(a[1]), "=r"(a[2]), "=r"(a[3]) : "r"(addr));
}
__device__ __forceinline__ void ldmB2(uint32_t b[2], uint32_t addr) {
    asm volatile("ldmatrix.sync.aligned.m8n8.x2.trans.shared.b16 {%0,%1}, [%2];"
                 : "=r"(b[0]), "=r"(b[1]) : "r"(addr));
}
__device__ __forceinline__ void mma16816(float c[4], const uint32_t a[4], const uint32_t b[2]) {
    asm volatile("mma.sync.aligned.m16n8k16.row.col.f32.bf16.bf16.f32 "
                 "{%0,%1,%2,%3}, {%4,%5,%6,%7}, {%8,%9}, {%0,%1,%2,%3};"
                 : "+f"(c[0]), "+f"(c[1]), "+f"(c[2]), "+f"(c[3])
                 : "r"(a[0]), "r"(a[1]), "r"(a[2]), "r"(a[3]), "r"(b[0]), "r"(b[1]));
}

// ---------------- CSR build ----------------
__global__ void k_init(int N, int G) {
    int i = blockIdx.x * blockDim.x + threadIdx.x;
    if (i < N) d_indeg[i] = 0;
    if (i <= G + 1) d_gstart[i] = N;
}

__global__ void k_count(const int* __restrict__ ei, int E) {
    int i = blockIdx.x * blockDim.x + threadIdx.x;
    if (i < E) atomicAdd(&d_indeg[ei[E + i]], 1);
}

__global__ void k_scan(int N) {
    __shared__ int sm[1024];
    int t = threadIdx.x;
    int chunk = (N + 1023) >> 10;
    int b = t * chunk, e = min(N, b + chunk);
    int s = 0;
    for (int i = b; i < e; i++) s += d_indeg[i];
    sm[t] = s;
    __syncthreads();
    for (int off = 1; off < 1024; off <<= 1) {
        int v = (t >= off) ? sm[t - off] : 0;
        __syncthreads();
        sm[t] += v;
        __syncthreads();
    }
    int run = sm[t] - s;
    for (int i = b; i < e; i++) {
        d_off[i] = run;
        d_cur[i] = run;
        run += d_indeg[i];
    }
}

__global__ void k_fill(const int* __restrict__ ei, int E) {
    int i = blockIdx.x * blockDim.x + threadIdx.x;
    if (i < E) {
        int s = ei[i];
        int d = ei[E + i];
        int p = atomicAdd(&d_cur[d], 1);
        d_csrc[p] = s;
    }
}

// ---------------- layers 1+2 analytic shortcuts ----------------
__global__ void k_const(const float* __restrict__ convw,
                        const float* __restrict__ wih,
                        const float* __restrict__ whh,
                        const float* __restrict__ bih,
                        const float* __restrict__ bhh) {
    __shared__ float x1[D], m2[D];
    int t = threadIdx.x;
    if (t < D) {
        float r = sigf(bih[t] + bhh[t]);
        float z = sigf(bih[64 + t] + bhh[64 + t]);
        float n = tanhf(bih[128 + t] + r * bhh[128 + t]);
        x1[t] = (1.0f - z) * n;
    }
    __syncthreads();
    if (t < D) {
        const float* w1 = convw + 1 * D * D;
        float s = 0.0f;
        for (int k = 0; k < D; k++) s += x1[k] * w1[k * D + t];
        m2[t] = s;
        d_x1row[t] = x1[t];
    }
    __syncthreads();
    if (t < C3) {
        const float* wih1 = wih + 1 * C3 * D;
        const float* whh1 = whh + 1 * C3 * D;
        const float* bhh1 = bhh + 1 * C3;
        float sq = 0.0f, sp = 0.0f;
        for (int j = 0; j < D; j++) {
            sq += m2[j] * wih1[t * D + j];
            sp += x1[j] * whh1[t * D + j];
        }
        d_q[t]  = sq;
        d_p2[t] = sp + bhh1[t];
    }
}

__global__ void k_layer2(const float* __restrict__ bih1, int N) {
    int idx = blockIdx.x * blockDim.x + threadIdx.x;
    if (idx >= N * D) return;
    int v = idx >> 6, d = idx & 63;
    float deg = (float)d_indeg[v];
    float r = sigf(deg * d_q[d]       + bih1[d]       + d_p2[d]);
    float z = sigf(deg * d_q[64 + d]  + bih1[64 + d]  + d_p2[64 + d]);
    float n = tanhf(deg * d_q[128 + d] + bih1[128 + d] + r * d_p2[128 + d]);
    d_xA[idx] = (1.0f - z) * n + z * d_x1row[d];
}

// ---------------- pre-pack bf16 hi/lo B blocks, gate-interleaved cols ----------------
__global__ void k_bprep(const float* __restrict__ convw,
                        const float* __restrict__ wih,
                        const float* __restrict__ whh) {
    int idx = blockIdx.x * blockDim.x + threadIdx.x;  // 3*2*192*64
    if (idx >= 73728) return;
    int l0 = idx / 24576;
    int rem = idx % 24576;
    int m = rem / 12288;
    int rem2 = rem % 12288;
    int c = rem2 >> 6;      // 0..191 (gate*64 + d)
    int k = rem2 & 63;
    int lg = l0 + 2;
    float val;
    if (m == 0) {
        const float* w  = convw + lg * D * D + k * D;
        const float* wi = wih   + lg * C3 * D + c * D;
        float s = 0.0f;
        for (int j = 0; j < D; j++) s += w[j] * wi[j];
        val = s;
    } else {
        val = whh[lg * C3 * D + c * D + k];
    }
    __nv_bfloat16 hi = __float2bfloat16(val);
    __nv_bfloat16 lo = __float2bfloat16(val - __bfloat162float(hi));
    int gate = c >> 6, d = c & 63;
    int w8 = d >> 3, t = d & 7;
    int jj = (m == 0) ? gate : gate + 3;
    int col = w8 * 48 + jj * 8 + t;
    d_Bk[l0][0][k][col] = hi;
    d_Bk[l0][1][k][col] = lo;
}

// ---------------- gather: S[v] = sum_{u in in(v)} x[u] ----------------
__global__ void k_gather(int cur, int N) {
    int w = (blockIdx.x * blockDim.x + threadIdx.x) >> 5;
    int lane = threadIdx.x & 31;
    if (w >= N) return;
    const float* x = cur ? d_xB : d_xA;
    int o = d_off[w], dg = d_indeg[w];
    float2 acc = make_float2(0.0f, 0.0f);
    for (int e = 0; e < dg; e++) {
        int u = d_csrc[o + e];
        float2 v = ((const float2*)(x + u * D))[lane];
        acc.x += v.x;
        acc.y += v.y;
    }
    ((float2*)(d_S + w * D))[lane] = acc;
}

// ---------------- HMMA fused GEMM + GRU (register epilogue) ----------------
// 256 threads, persistent, tile = 128 nodes, B resident in smem.
// Warp w owns dims 8w..8w+7: j=0..2 gi gates (A=S), j=3..5 gh gates (A=X).
// 3-term bf16 split: Ah*Bh + Al*Bh + Ah*Bl.
#define BP 392            // B smem pitch (bf16): 784B
#define AP 72             // A smem pitch (bf16): 144B
#define SM_BHI 0
#define SM_BLO 50176
#define SM_SHI 100352
#define SM_SLO 118784
#define SM_XHI 137216
#define SM_XLO 155648
#define SM_TOT 174080

__global__ void __launch_bounds__(256, 1) k_gemm_gru_mma(int cur, int l, int N,
                                                         const float* __restrict__ bih,
                                                         const float* __restrict__ bhh) {
    extern __shared__ char smem[];
    uint32_t sb = smem_u32(smem);
    int tid = threadIdx.x, wid = tid >> 5, lane = tid & 31;
    const float* Xin  = cur ? d_xB : d_xA;
    float*       Xout = cur ? d_xA : d_xB;

    // ---- load resident B (hi/lo), pitch BP ----
    {
        const int4* srcH = (const int4*)(&d_Bk[l][0][0][0]);
        const int4* srcL = (const int4*)(&d_Bk[l][1][0][0]);
        for (int i = tid; i < 3072; i += 256) {
            int row = i / 48, cb = i % 48;
            *(int4*)(smem + SM_BHI + row * (BP * 2) + cb * 16) = srcH[i];
            *(int4*)(smem + SM_BLO + row * (BP * 2) + cb * 16) = srcL[i];
        }
    }

    // per-thread ldmatrix offsets
    uint32_t aoff = (uint32_t)(lane & 15) * (AP * 2) + ((lane >> 4) << 3) * 2;
    uint32_t boff = (uint32_t)(lane & 15) * (BP * 2);
    int wcol = wid * 48;
    int gID = lane >> 2, tig = lane & 3;
    int d0 = wid * 8 + 2 * tig;    // this thread's two feature dims: d0, d0+1

    // preload biases for d0/d0+1 (all 6 gates)
    float bir0 = __ldg(&bih[d0]),        bir1 = __ldg(&bih[d0 + 1]);
    float biz0 = __ldg(&bih[64 + d0]),   biz1 = __ldg(&bih[64 + d0 + 1]);
    float bin0 = __ldg(&bih[128 + d0]),  bin1 = __ldg(&bih[128 + d0 + 1]);
    float bhr0 = __ldg(&bhh[d0]),        bhr1 = __ldg(&bhh[d0 + 1]);
    float bhz0 = __ldg(&bhh[64 + d0]),   bhz1 = __ldg(&bhh[64 + d0 + 1]);
    float bhn0 = __ldg(&bhh[128 + d0]),  bhn1 = __ldg(&bhh[128 + d0 + 1]);

    int ntiles = (N + 127) >> 7;
    for (int tile = blockIdx.x; tile < ntiles; tile += gridDim.x) {
        int n0 = tile << 7;
        __syncthreads();   // previous tile's A reads complete before overwrite

        // ---- stage A: fp32 S|X -> bf16 hi/lo ----
        for (int i = tid; i < 4096; i += 256) {   // 128 nodes x 32 float2
            int node = i >> 5, kp = i & 31;
            int gn = n0 + node;
            float2 s = make_float2(0.f, 0.f), x = make_float2(0.f, 0.f);
            if (gn < N) {
                s = __ldg((const float2*)(d_S + gn * 64) + kp);
                x = __ldg((const float2*)(Xin + gn * 64) + kp);
            }
            __nv_bfloat162 sh = __float22bfloat162_rn(s);
            float2 shf = __bfloat1622float2(sh);
            __nv_bfloat162 sl = __float22bfloat162_rn(make_float2(s.x - shf.x, s.y - shf.y));
            __nv_bfloat162 xh = __float22bfloat162_rn(x);
            float2 xhf = __bfloat1622float2(xh);
            __nv_bfloat162 xl = __float22bfloat162_rn(make_float2(x.x - xhf.x, x.y - xhf.y));
            uint32_t off = (uint32_t)node * (AP * 2) + kp * 4;
            *(uint32_t*)(smem + SM_SHI + off) = *(uint32_t*)&sh;
            *(uint32_t*)(smem + SM_SLO + off) = *(uint32_t*)&sl;
            *(uint32_t*)(smem + SM_XHI + off) = *(uint32_t*)&xh;
            *(uint32_t*)(smem + SM_XLO + off) = *(uint32_t*)&xl;
        }
        __syncthreads();

        for (int mc = 0; mc < 4; mc++) {
            int m0 = mc * 32;

            float c[2][6][4];
            #pragma unroll
            for (int mf = 0; mf < 2; mf++)
                #pragma unroll
                for (int j = 0; j < 6; j++)
                    #pragma unroll
                    for (int q = 0; q < 4; q++) c[mf][j][q] = 0.0f;

            #pragma unroll
            for (int ks = 0; ks < 4; ks++) {
                int k0 = ks * 16;
                uint32_t abase = (uint32_t)m0 * (AP * 2) + k0 * 2 + aoff;
                uint32_t sh[2][4], sl[2][4], xh[2][4], xl[2][4];
                ldmA4(sh[0], sb + SM_SHI + abase);
                ldmA4(sh[1], sb + SM_SHI + abase + 16 * (AP * 2));
                ldmA4(sl[0], sb + SM_SLO + abase);
                ldmA4(sl[1], sb + SM_SLO + abase + 16 * (AP * 2));
                ldmA4(xh[0], sb + SM_XHI + abase);
                ldmA4(xh[1], sb + SM_XHI + abase + 16 * (AP * 2));
                ldmA4(xl[0], sb + SM_XLO + abase);
                ldmA4(xl[1], sb + SM_XLO + abase + 16 * (AP * 2));
                #pragma unroll
                for (int j = 0; j < 6; j++) {
                    uint32_t bh[2], bl[2];
                    uint32_t bbase = (uint32_t)k0 * (BP * 2) + (wcol + 8 * j) * 2 + boff;
                    ldmB2(bh, sb + SM_BHI + bbase);
                    ldmB2(bl, sb + SM_BLO + bbase);
                    const uint32_t (*h)[4] = (j < 3) ? sh : xh;
                    const uint32_t (*lo)[4] = (j < 3) ? sl : xl;
                    mma16816(c[0][j], h[0], bh);
                    mma16816(c[1][j], h[1], bh);
                    mma16816(c[0][j], lo[0], bh);
                    mma16816(c[1][j], lo[1], bh);
                    mma16816(c[0][j], h[0], bl);
                    mma16816(c[1][j], h[1], bl);
                }
            }

            // ---- register GRU epilogue ----
            #pragma unroll
            for (int mf = 0; mf < 2; mf++) {
                #pragma unroll
                for (int half = 0; half < 2; half++) {
                    int r = m0 + mf * 16 + gID + half * 8;
                    int node = n0 + r;
                    if (node < N) {
                        int q0 = half * 2, q1 = q0 + 1;
                        float2 xi = __ldg(((const float2*)(Xin + node * 64)) + (d0 >> 1));
                        float rr0 = sigf(c[mf][0][q0] + bir0 + c[mf][3][q0] + bhr0);
                        float zz0 = sigf(c[mf][1][q0] + biz0 + c[mf][4][q0] + bhz0);
                        float nn0 = tanhf(c[mf][2][q0] + bin0 + rr0 * (c[mf][5][q0] + bhn0));
                        float o0 = (1.0f - zz0) * nn0 + zz0 * xi.x;
                        float rr1 = sigf(c[mf][0][q1] + bir1 + c[mf][3][q1] + bhr1);
                        float zz1 = sigf(c[mf][1][q1] + biz1 + c[mf][4][q1] + bhz1);
                        float nn1 = tanhf(c[mf][2][q1] + bin1 + rr1 * (c[mf][5][q1] + bhn1));
                        float o1 = (1.0f - zz1) * nn1 + zz1 * xi.y;
                        ((float2*)(Xout + node * 64))[d0 >> 1] = make_float2(o0, o1);
                    }
                }
            }
        }
    }
}

// ---------------- segmented pooling (batch is sorted) ----------------
__global__ void k_gstart(const int* __restrict__ batch, int N) {
    int i = blockIdx.x * blockDim.x + threadIdx.x;
    if (i < N) atomicMin(&d_gstart[batch[i]], i);
}

__global__ void k_gfix(int G, int N) {
    d_gstart[G] = N;
    for (int g = G - 1; g >= 0; g--)
        if (d_gstart[g] > d_gstart[g + 1]) d_gstart[g] = d_gstart[g + 1];
}

__global__ void k_pool2(int cur, int N) {
    __shared__ float red[256];
    const float* x = cur ? d_xB : d_xA;
    int g = blockIdx.x;
    int t = threadIdx.x;
    int d = t & 63, part = t >> 6;
    int s = d_gstart[g], e = d_gstart[g + 1];
    float acc = 0.0f;
    for (int n = s + part; n < e; n += 4) acc += x[n * D + d];
    red[t] = acc;
    __syncthreads();
    if (t < 64)
        d_pool[g * D + t] = red[t] + red[64 + t] + red[128 + t] + red[192 + t];
}

__global__ void k_mlp(const float* __restrict__ w1, const float* __restrict__ b1,
                      const float* __restrict__ w2, const float* __restrict__ b2,
                      const float* __restrict__ w3, const float* __restrict__ b3,
                      float* __restrict__ out) {
    __shared__ float h1[32], h2[16];
    int g = blockIdx.x, t = threadIdx.x;
    if (t < 32) {
        float s = b1[t];
        for (int k = 0; k < D; k++) s += d_pool[g * D + k] * w1[t * D + k];
        h1[t] = (s > 0.0f) ? s : expm1f(s);
    }
    __syncthreads();
    if (t < 16) {
        float s = b2[t];
        for (int k = 0; k < 32; k++) s += h1[k] * w2[t * 32 + k];
        h2[t] = (s > 0.0f) ? s : expm1f(s);
    }
    __syncthreads();
    if (t == 0) {
        float s = b3[0];
        for (int k = 0; k < 16; k++) s += h2[k] * w3[k];
        out[g] = s;
    }
}

// ---------------- launch ----------------
extern "C" void kernel_launch(void* const* d_in, const int* in_sizes, int n_in,
                              void* d_out, int out_size) {
    const float* convw = (const float*)d_in[0];
    const float* wih   = (const float*)d_in[1];
    const float* whh   = (const float*)d_in[2];
    const float* bih   = (const float*)d_in[3];
    const float* bhh   = (const float*)d_in[4];
    const float* fc1w  = (const float*)d_in[5];
    const float* fc1b  = (const float*)d_in[6];
    const float* fc2w  = (const float*)d_in[7];
    const float* fc2b  = (const float*)d_in[8];
    const float* fc3w  = (const float*)d_in[9];
    const float* fc3b  = (const float*)d_in[10];
    const int*   ei    = (const int*)d_in[11];
    const int*   batch = (const int*)d_in[12];

    int E = in_sizes[11] / 2;
    int N = in_sizes[12];
    int G = out_size;
    float* out = (float*)d_out;

    static int smem_set = 0;
    if (!smem_set) {
        cudaFuncSetAttribute(k_gemm_gru_mma, cudaFuncAttributeMaxDynamicSharedMemorySize, SM_TOT);
        smem_set = 1;
    }

    int tb = 256;
    int gN    = (N + tb - 1) / tb;
    int gE    = (E + tb - 1) / tb;
    int gND   = (N * D + tb - 1) / tb;
    int gWarp = (N * 32 + tb - 1) / tb;

    // CSR build + graph ranges
    k_init<<<gN, tb>>>(N, G);
    k_count<<<gE, tb>>>(ei, E);
    k_scan<<<1, 1024>>>(N);
    k_fill<<<gE, tb>>>(ei, E);
    k_gstart<<<gN, tb>>>(batch, N);
    k_gfix<<<1, 1>>>(G, N);

    // analytic layers 1+2 and B packing
    k_const<<<1, 192>>>(convw, wih, whh, bih, bhh);
    k_layer2<<<gND, tb>>>(bih + C3, N);           // writes d_xA (cur=0)
    k_bprep<<<(73728 + tb - 1) / tb, tb>>>(convw, wih, whh);

    // layers 3..5: gather + HMMA fused GEMM+GRU (register epilogue), ping-pong
    int cur = 0;
    for (int l = 0; l < 3; l++) {
        int lg = l + 2;
        k_gather<<<gWarp, tb>>>(cur, N);
        k_gemm_gru_mma<<<148, 256, SM_TOT>>>(cur, l, N, bih + lg * C3, bhh + lg * C3);
        cur ^= 1;
    }

    // pooling + MLP head
    k_pool2<<<G, 256>>>(cur, N);
    k_mlp<<<G, 64>>>(fc1w, fc1b, fc2w, fc2b, fc3w, fc3b, out);
}

// round 10
// speedup vs baseline: 1.9351x; 1.1916x over previous
#include <cuda_runtime.h>
#include <cuda_fp16.h>
#include <math.h>
#include <stdint.h>

#define D   64
#define C3  192
#define MAXN 100352
#define MAXE 1600064

// ---------------- device scratch (static, no allocation) ----------------
__device__ float d_xA[MAXN * D];
__device__ float d_xB[MAXN * D];
__device__ float d_S [MAXN * D];
__device__ int   d_indeg[MAXN];
__device__ int   d_off  [MAXN];
__device__ int   d_cur  [MAXN];
__device__ int   d_csrc [MAXE];
// Packed fp16 B per layer l=0..2 (global 2..4): [k=0..63][col'=0..383]
// col' = w*48 + j*8 + t : warp w owns dims 8w..8w+7; j=0..2 gi gates (r,z,n), j=3..5 gh gates
__device__ __align__(16) __half d_Bk[3][64][384];
__device__ float d_q[C3], d_p2[C3], d_x1row[D];
__device__ float d_pool[64 * D];
__device__ int   d_gstart[66];

__device__ __forceinline__ float sigf(float x) { return 1.0f / (1.0f + expf(-x)); }

__device__ __forceinline__ uint32_t smem_u32(const void* p) {
    uint32_t a;
    asm("{ .reg .u64 t; cvta.to.shared.u64 t, %1; cvt.u32.u64 %0, t; }" : "=r"(a) : "l"(p));
    return a;
}
__device__ __forceinline__ void ldmA4(uint32_t a[4], uint32_t addr) {
    asm volatile("ldmatrix.sync.aligned.m8n8.x4.shared.b16 {%0,%1,%2,%3}, [%4];"
                 : "=r"(a[0]), "=r"(a[1]), "=r"(a[2]), "=r"(a[3]) : "r"(addr));
}
__device__ __forceinline__ void ldmB2(uint32_t b[2], uint32_t addr) {
    asm volatile("ldmatrix.sync.aligned.m8n8.x2.trans.shared.b16 {%0,%1}, [%2];"
                 : "=r"(b[0]), "=r"(b[1]) : "r"(addr));
}
__device__ __forceinline__ void mma16816(float c[4], const uint32_t a[4], const uint32_t b[2]) {
    asm volatile("mma.sync.aligned.m16n8k16.row.col.f32.f16.f16.f32 "
                 "{%0,%1,%2,%3}, {%4,%5,%6,%7}, {%8,%9}, {%0,%1,%2,%3};"
                 : "+f"(c[0]), "+f"(c[1]), "+f"(c[2]), "+f"(c[3])
                 : "r"(a[0]), "r"(a[1]), "r"(a[2]), "r"(a[3]), "r"(b[0]), "r"(b[1]));
}

// ---------------- CSR build ----------------
__global__ void k_init(int N, int G) {
    int i = blockIdx.x * blockDim.x + threadIdx.x;
    if (i < N) d_indeg[i] = 0;
    if (i <= G + 1) d_gstart[i] = N;
}

__global__ void k_count(const int* __restrict__ ei, int E) {
    int i = blockIdx.x * blockDim.x + threadIdx.x;
    if (i < E) atomicAdd(&d_indeg[ei[E + i]], 1);
}

__global__ void k_scan(int N) {
    __shared__ int sm[1024];
    int t = threadIdx.x;
    int chunk = (N + 1023) >> 10;
    int b = t * chunk, e = min(N, b + chunk);
    int s = 0;
    for (int i = b; i < e; i++) s += d_indeg[i];
    sm[t] = s;
    __syncthreads();
    for (int off = 1; off < 1024; off <<= 1) {
        int v = (t >= off) ? sm[t - off] : 0;
        __syncthreads();
        sm[t] += v;
        __syncthreads();
    }
    int run = sm[t] - s;
    for (int i = b; i < e; i++) {
        d_off[i] = run;
        d_cur[i] = run;
        run += d_indeg[i];
    }
}

__global__ void k_fill(const int* __restrict__ ei, int E) {
    int i = blockIdx.x * blockDim.x + threadIdx.x;
    if (i < E) {
        int s = ei[i];
        int d = ei[E + i];
        int p = atomicAdd(&d_cur[d], 1);
        d_csrc[p] = s;
    }
}

// ---------------- layers 1+2 analytic shortcuts ----------------
__global__ void k_const(const float* __restrict__ convw,
                        const float* __restrict__ wih,
                        const float* __restrict__ whh,
                        const float* __restrict__ bih,
                        const float* __restrict__ bhh) {
    __shared__ float x1[D], m2[D];
    int t = threadIdx.x;
    if (t < D) {
        float r = sigf(bih[t] + bhh[t]);
        float z = sigf(bih[64 + t] + bhh[64 + t]);
        float n = tanhf(bih[128 + t] + r * bhh[128 + t]);
        x1[t] = (1.0f - z) * n;
    }
    __syncthreads();
    if (t < D) {
        const float* w1 = convw + 1 * D * D;
        float s = 0.0f;
        for (int k = 0; k < D; k++) s += x1[k] * w1[k * D + t];
        m2[t] = s;
        d_x1row[t] = x1[t];
    }
    __syncthreads();
    if (t < C3) {
        const float* wih1 = wih + 1 * C3 * D;
        const float* whh1 = whh + 1 * C3 * D;
        const float* bhh1 = bhh + 1 * C3;
        float sq = 0.0f, sp = 0.0f;
        for (int j = 0; j < D; j++) {
            sq += m2[j] * wih1[t * D + j];
            sp += x1[j] * whh1[t * D + j];
        }
        d_q[t]  = sq;
        d_p2[t] = sp + bhh1[t];
    }
}

__global__ void k_layer2(const float* __restrict__ bih1, int N) {
    int idx = blockIdx.x * blockDim.x + threadIdx.x;
    if (idx >= N * D) return;
    int v = idx >> 6, d = idx & 63;
    float deg = (float)d_indeg[v];
    float r = sigf(deg * d_q[d]       + bih1[d]       + d_p2[d]);
    float z = sigf(deg * d_q[64 + d]  + bih1[64 + d]  + d_p2[64 + d]);
    float n = tanhf(deg * d_q[128 + d] + bih1[128 + d] + r * d_p2[128 + d]);
    d_xA[idx] = (1.0f - z) * n + z * d_x1row[d];
}

// ---------------- pre-pack fp16 B, gate-interleaved cols ----------------
__global__ void k_bprep(const float* __restrict__ convw,
                        const float* __restrict__ wih,
                        const float* __restrict__ whh) {
    int idx = blockIdx.x * blockDim.x + threadIdx.x;  // 3*2*192*64
    if (idx >= 73728) return;
    int l0 = idx / 24576;
    int rem = idx % 24576;
    int m = rem / 12288;
    int rem2 = rem % 12288;
    int c = rem2 >> 6;      // 0..191 (gate*64 + d)
    int k = rem2 & 63;
    int lg = l0 + 2;
    float val;
    if (m == 0) {
        const float* w  = convw + lg * D * D + k * D;
        const float* wi = wih   + lg * C3 * D + c * D;
        float s = 0.0f;
        for (int j = 0; j < D; j++) s += w[j] * wi[j];
        val = s;
    } else {
        val = whh[lg * C3 * D + c * D + k];
    }
    int gate = c >> 6, d = c & 63;
    int w8 = d >> 3, t = d & 7;
    int jj = (m == 0) ? gate : gate + 3;
    int col = w8 * 48 + jj * 8 + t;
    d_Bk[l0][k][col] = __float2half_rn(val);
}

// ---------------- gather: S[v] = sum_{u in in(v)} x[u] ----------------
__global__ void k_gather(int cur, int N) {
    int w = (blockIdx.x * blockDim.x + threadIdx.x) >> 5;
    int lane = threadIdx.x & 31;
    if (w >= N) return;
    const float* x = cur ? d_xB : d_xA;
    int o = d_off[w], dg = d_indeg[w];
    float2 acc = make_float2(0.0f, 0.0f);
    for (int e = 0; e < dg; e++) {
        int u = d_csrc[o + e];
        float2 v = ((const float2*)(x + u * D))[lane];
        acc.x += v.x;
        acc.y += v.y;
    }
    ((float2*)(d_S + w * D))[lane] = acc;
}

// ---------------- HMMA fused GEMM + GRU (fp16 2-term, 512 threads) ----------------
// 512 threads = 16 warps. Warp group wid&7 owns dims 8(wid&7)..+7 (cols wcol..wcol+47);
// warps 0-7 do node chunks mc=0,1; warps 8-15 do mc=2,3.
// A = (Ah + Al) fp16 split; B = fp16 RN. 2-term: Ah*B + Al*B.
#define BP 392            // B smem pitch (halves): 784B
#define AP 72             // A smem pitch (halves): 144B
#define SM_BHI 0
#define SM_SHI 50176
#define SM_SLO 68608
#define SM_XHI 87040
#define SM_XLO 105472
#define SM_TOT 123904

__global__ void __launch_bounds__(512, 1) k_gemm_gru_mma(int cur, int l, int N,
                                                         const float* __restrict__ bih,
                                                         const float* __restrict__ bhh) {
    extern __shared__ char smem[];
    uint32_t sb = smem_u32(smem);
    int tid = threadIdx.x, wid = tid >> 5, lane = tid & 31;
    int wid8 = wid & 7, mch = wid >> 3;
    const float* Xin  = cur ? d_xB : d_xA;
    float*       Xout = cur ? d_xA : d_xB;

    // ---- load resident B (fp16), pitch BP ----
    {
        const int4* src = (const int4*)(&d_Bk[l][0][0]);
        for (int i = tid; i < 3072; i += 512) {    // 64 rows x 48 int4
            int row = i / 48, cb = i % 48;
            *(int4*)(smem + SM_BHI + row * (BP * 2) + cb * 16) = src[i];
        }
    }

    // per-thread ldmatrix offsets
    uint32_t aoff = (uint32_t)(lane & 15) * (AP * 2) + ((lane >> 4) << 3) * 2;
    uint32_t boff = (uint32_t)(lane & 15) * (BP * 2);
    int wcol = wid8 * 48;
    int gID = lane >> 2, tig = lane & 3;
    int d0 = wid8 * 8 + 2 * tig;   // this thread's two feature dims

    // preload biases (all 6 gates for d0, d0+1)
    float bir0 = __ldg(&bih[d0]),        bir1 = __ldg(&bih[d0 + 1]);
    float biz0 = __ldg(&bih[64 + d0]),   biz1 = __ldg(&bih[64 + d0 + 1]);
    float bin0 = __ldg(&bih[128 + d0]),  bin1 = __ldg(&bih[128 + d0 + 1]);
    float bhr0 = __ldg(&bhh[d0]),        bhr1 = __ldg(&bhh[d0 + 1]);
    float bhz0 = __ldg(&bhh[64 + d0]),   bhz1 = __ldg(&bhh[64 + d0 + 1]);
    float bhn0 = __ldg(&bhh[128 + d0]),  bhn1 = __ldg(&bhh[128 + d0 + 1]);

    int ntiles = (N + 127) >> 7;
    for (int tile = blockIdx.x; tile < ntiles; tile += gridDim.x) {
        int n0 = tile << 7;
        __syncthreads();   // previous tile's A reads complete before overwrite

        // ---- stage A: fp32 S|X -> fp16 hi/lo ----
        for (int i = tid; i < 4096; i += 512) {    // 128 nodes x 32 float2
            int node = i >> 5, kp = i & 31;
            int gn = n0 + node;
            float2 s = make_float2(0.f, 0.f), x = make_float2(0.f, 0.f);
            if (gn < N) {
                s = __ldg((const float2*)(d_S + gn * 64) + kp);
                x = __ldg((const float2*)(Xin + gn * 64) + kp);
            }
            __half2 sh = __float22half2_rn(s);
            float2 shf = __half22float2(sh);
            __half2 sl = __float22half2_rn(make_float2(s.x - shf.x, s.y - shf.y));
            __half2 xh = __float22half2_rn(x);
            float2 xhf = __half22float2(xh);
            __half2 xl = __float22half2_rn(make_float2(x.x - xhf.x, x.y - xhf.y));
            uint32_t off = (uint32_t)node * (AP * 2) + kp * 4;
            *(uint32_t*)(smem + SM_SHI + off) = *(uint32_t*)&sh;
            *(uint32_t*)(smem + SM_SLO + off) = *(uint32_t*)&sl;
            *(uint32_t*)(smem + SM_XHI + off) = *(uint32_t*)&xh;
            *(uint32_t*)(smem + SM_XLO + off) = *(uint32_t*)&xl;
        }
        __syncthreads();

        #pragma unroll
        for (int mi = 0; mi < 2; mi++) {
            int m0 = (mch * 2 + mi) * 32;

            float c[2][6][4];
            #pragma unroll
            for (int mf = 0; mf < 2; mf++)
                #pragma unroll
                for (int j = 0; j < 6; j++)
                    #pragma unroll
                    for (int q = 0; q < 4; q++) c[mf][j][q] = 0.0f;

            #pragma unroll
            for (int ks = 0; ks < 4; ks++) {
                int k0 = ks * 16;
                uint32_t abase = (uint32_t)m0 * (AP * 2) + k0 * 2 + aoff;
                uint32_t sh[2][4], sl[2][4], xh[2][4], xl[2][4];
                ldmA4(sh[0], sb + SM_SHI + abase);
                ldmA4(sh[1], sb + SM_SHI + abase + 16 * (AP * 2));
                ldmA4(sl[0], sb + SM_SLO + abase);
                ldmA4(sl[1], sb + SM_SLO + abase + 16 * (AP * 2));
                ldmA4(xh[0], sb + SM_XHI + abase);
                ldmA4(xh[1], sb + SM_XHI + abase + 16 * (AP * 2));
                ldmA4(xl[0], sb + SM_XLO + abase);
                ldmA4(xl[1], sb + SM_XLO + abase + 16 * (AP * 2));
                #pragma unroll
                for (int j = 0; j < 6; j++) {
                    uint32_t bh[2];
                    uint32_t bbase = (uint32_t)k0 * (BP * 2) + (wcol + 8 * j) * 2 + boff;
                    ldmB2(bh, sb + SM_BHI + bbase);
                    const uint32_t (*h)[4]  = (j < 3) ? sh : xh;
                    const uint32_t (*lo)[4] = (j < 3) ? sl : xl;
                    mma16816(c[0][j], h[0], bh);
                    mma16816(c[1][j], h[1], bh);
                    mma16816(c[0][j], lo[0], bh);
                    mma16816(c[1][j], lo[1], bh);
                }
            }

            // ---- register GRU epilogue ----
            #pragma unroll
            for (int mf = 0; mf < 2; mf++) {
                #pragma unroll
                for (int half = 0; half < 2; half++) {
                    int r = m0 + mf * 16 + gID + half * 8;
                    int node = n0 + r;
                    if (node < N) {
                        int q0 = half * 2, q1 = q0 + 1;
                        float2 xi = __ldg(((const float2*)(Xin + node * 64)) + (d0 >> 1));
                        float rr0 = sigf(c[mf][0][q0] + bir0 + c[mf][3][q0] + bhr0);
                        float zz0 = sigf(c[mf][1][q0] + biz0 + c[mf][4][q0] + bhz0);
                        float nn0 = tanhf(c[mf][2][q0] + bin0 + rr0 * (c[mf][5][q0] + bhn0));
                        float o0 = (1.0f - zz0) * nn0 + zz0 * xi.x;
                        float rr1 = sigf(c[mf][0][q1] + bir1 + c[mf][3][q1] + bhr1);
                        float zz1 = sigf(c[mf][1][q1] + biz1 + c[mf][4][q1] + bhz1);
                        float nn1 = tanhf(c[mf][2][q1] + bin1 + rr1 * (c[mf][5][q1] + bhn1));
                        float o1 = (1.0f - zz1) * nn1 + zz1 * xi.y;
                        ((float2*)(Xout + node * 64))[d0 >> 1] = make_float2(o0, o1);
                    }
                }
            }
        }
    }
}

// ---------------- segmented pooling (batch is sorted) ----------------
__global__ void k_gstart(const int* __restrict__ batch, int N) {
    int i = blockIdx.x * blockDim.x + threadIdx.x;
    if (i < N) atomicMin(&d_gstart[batch[i]], i);
}

__global__ void k_gfix(int G, int N) {
    d_gstart[G] = N;
    for (int g = G - 1; g >= 0; g--)
        if (d_gstart[g] > d_gstart[g + 1]) d_gstart[g] = d_gstart[g + 1];
}

__global__ void k_pool2(int cur, int N) {
    __shared__ float red[256];
    const float* x = cur ? d_xB : d_xA;
    int g = blockIdx.x;
    int t = threadIdx.x;
    int d = t & 63, part = t >> 6;
    int s = d_gstart[g], e = d_gstart[g + 1];
    float acc = 0.0f;
    for (int n = s + part; n < e; n += 4) acc += x[n * D + d];
    red[t] = acc;
    __syncthreads();
    if (t < 64)
        d_pool[g * D + t] = red[t] + red[64 + t] + red[128 + t] + red[192 + t];
}

__global__ void k_mlp(const float* __restrict__ w1, const float* __restrict__ b1,
                      const float* __restrict__ w2, const float* __restrict__ b2,
                      const float* __restrict__ w3, const float* __restrict__ b3,
                      float* __restrict__ out) {
    __shared__ float h1[32], h2[16];
    int g = blockIdx.x, t = threadIdx.x;
    if (t < 32) {
        float s = b1[t];
        for (int k = 0; k < D; k++) s += d_pool[g * D + k] * w1[t * D + k];
        h1[t] = (s > 0.0f) ? s : expm1f(s);
    }
    __syncthreads();
    if (t < 16) {
        float s = b2[t];
        for (int k = 0; k < 32; k++) s += h1[k] * w2[t * 32 + k];
        h2[t] = (s > 0.0f) ? s : expm1f(s);
    }
    __syncthreads();
    if (t == 0) {
        float s = b3[0];
        for (int k = 0; k < 16; k++) s += h2[k] * w3[k];
        out[g] = s;
    }
}

// ---------------- launch ----------------
extern "C" void kernel_launch(void* const* d_in, const int* in_sizes, int n_in,
                              void* d_out, int out_size) {
    const float* convw = (const float*)d_in[0];
    const float* wih   = (const float*)d_in[1];
    const float* whh   = (const float*)d_in[2];
    const float* bih   = (const float*)d_in[3];
    const float* bhh   = (const float*)d_in[4];
    const float* fc1w  = (const float*)d_in[5];
    const float* fc1b  = (const float*)d_in[6];
    const float* fc2w  = (const float*)d_in[7];
    const float* fc2b  = (const float*)d_in[8];
    const float* fc3w  = (const float*)d_in[9];
    const float* fc3b  = (const float*)d_in[10];
    const int*   ei    = (const int*)d_in[11];
    const int*   batch = (const int*)d_in[12];

    int E = in_sizes[11] / 2;
    int N = in_sizes[12];
    int G = out_size;
    float* out = (float*)d_out;

    static int smem_set = 0;
    if (!smem_set) {
        cudaFuncSetAttribute(k_gemm_gru_mma, cudaFuncAttributeMaxDynamicSharedMemorySize, SM_TOT);
        smem_set = 1;
    }

    int tb = 256;
    int gN    = (N + tb - 1) / tb;
    int gE    = (E + tb - 1) / tb;
    int gND   = (N * D + tb - 1) / tb;
    int gWarp = (N * 32 + tb - 1) / tb;

    // CSR build + graph ranges
    k_init<<<gN, tb>>>(N, G);
    k_count<<<gE, tb>>>(ei, E);
    k_scan<<<1, 1024>>>(N);
    k_fill<<<gE, tb>>>(ei, E);
    k_gstart<<<gN, tb>>>(batch, N);
    k_gfix<<<1, 1>>>(G, N);

    // analytic layers 1+2 and B packing
    k_const<<<1, 192>>>(convw, wih, whh, bih, bhh);
    k_layer2<<<gND, tb>>>(bih + C3, N);           // writes d_xA (cur=0)
    k_bprep<<<(73728 + tb - 1) / tb, tb>>>(convw, wih, whh);

    // layers 3..5: gather + HMMA fused GEMM+GRU, ping-pong
    int cur = 0;
    for (int l = 0; l < 3; l++) {
        int lg = l + 2;
        k_gather<<<gWarp, tb>>>(cur, N);
        k_gemm_gru_mma<<<148, 512, SM_TOT>>>(cur, l, N, bih + lg * C3, bhh + lg * C3);
        cur ^= 1;
    }

    // pooling + MLP head
    k_pool2<<<G, 256>>>(cur, N);
    k_mlp<<<G, 64>>>(fc1w, fc1b, fc2w, fc2b, fc3w, fc3b, out);
}